// round 5
// baseline (speedup 1.0000x reference)
#include <cuda_runtime.h>
#include <cuda_fp16.h>
#include <cstdint>

// ---------------- problem constants ----------------
#define IN_F    4096
#define OUT_F   11008
#define M_ROWS  8192
#define N_PACKED 22544384          // one packed byte per int32

// ---------------- GEMM tiling ----------------
#define BM 256
#define BN 128
#define BK 64                      // 64 fp16 = 128 B per smem row
#define NSTAGES 3
#define NK_TILES (IN_F / BK)       // 64
#define THREADS 256                // 8 warps: 4 (m) x 2 (n), warp tile 64x64

#define A_STAGE_BYTES (BM * 128)   // 32768
#define B_STAGE_BYTES (BN * 128)   // 16384
#define A_OFF 0
#define B_OFF (NSTAGES * A_STAGE_BYTES)                 // 98304
#define SMEM_BYTES (B_OFF + NSTAGES * B_STAGE_BYTES)    // 147456

// fp16 scratch (device globals = allowed scratch): W 90MB, x 64MB
static __device__ __half g_wdeq[(size_t)IN_F * (size_t)OUT_F];
static __device__ __half g_xh[(size_t)M_ROWS * (size_t)IN_F];

// ---------------- helpers ----------------
__device__ __forceinline__ uint32_t smem_u32(const void* p) {
    uint32_t a;
    asm("{ .reg .u64 t; cvta.to.shared.u64 t, %1; cvt.u32.u64 %0, t; }"
        : "=r"(a) : "l"(p));
    return a;
}

#define CP_ASYNC16(smem_addr, gptr) \
    asm volatile("cp.async.cg.shared.global.L2::128B [%0], [%1], 16;" \
                 :: "r"(smem_addr), "l"(gptr) : "memory")

#define CP_COMMIT() asm volatile("cp.async.commit_group;" ::: "memory")
#define CP_WAIT1()  asm volatile("cp.async.wait_group 1;" ::: "memory")

#define LDMATRIX_X4(r0, r1, r2, r3, addr) \
    asm volatile("ldmatrix.sync.aligned.m8n8.x4.shared.b16 {%0,%1,%2,%3}, [%4];" \
                 : "=r"(r0), "=r"(r1), "=r"(r2), "=r"(r3) : "r"(addr))

#define MMA_16816(c, a0, a1, a2, a3, b0, b1) \
    asm volatile("mma.sync.aligned.m16n8k16.row.col.f32.f16.f16.f32 " \
                 "{%0,%1,%2,%3}, {%4,%5,%6,%7}, {%8,%9}, {%0,%1,%2,%3};" \
                 : "+f"((c)[0]), "+f"((c)[1]), "+f"((c)[2]), "+f"((c)[3]) \
                 : "r"(a0), "r"(a1), "r"(a2), "r"(a3), "r"(b0), "r"(b1))

// ---------------- kernel 0: x f32 -> f16 (exact; x was originally f16) ----
__global__ __launch_bounds__(256)
void convert_x_kernel(const float* __restrict__ x) {
    size_t t = (size_t)blockIdx.x * blockDim.x + threadIdx.x;  // 8 elems/thread
    const float4* src = reinterpret_cast<const float4*>(x) + t * 2;
    float4 f0 = src[0], f1 = src[1];
    __half h[8];
    h[0] = __float2half_rn(f0.x); h[1] = __float2half_rn(f0.y);
    h[2] = __float2half_rn(f0.z); h[3] = __float2half_rn(f0.w);
    h[4] = __float2half_rn(f1.x); h[5] = __float2half_rn(f1.y);
    h[6] = __float2half_rn(f1.z); h[7] = __float2half_rn(f1.w);
    reinterpret_cast<uint4*>(g_xh)[t] = *reinterpret_cast<uint4*>(h);
}

// ---------------- kernel 1: dequant int4 -> fp16 ----------------
// Each thread: 4 packed bytes (one uint4 of int32s) -> 8 fp16 weights.
// Flat base 8t never straddles a group of 128.
__global__ __launch_bounds__(256)
void q4_dequant_kernel(const int* __restrict__ qw,
                       const float* __restrict__ scales,
                       const float* __restrict__ zeros) {
    int t = blockIdx.x * blockDim.x + threadIdx.x;     // < N_PACKED/4
    uint4 q = reinterpret_cast<const uint4*>(qw)[t];
    int g = (t << 3) >> 7;                             // group index
    float s = __ldg(scales + g);
    float z = __ldg(zeros + g);
    unsigned bs[4] = {q.x, q.y, q.z, q.w};
    __half h[8];
#pragma unroll
    for (int j = 0; j < 4; ++j) {
        int lo = (int)(bs[j] & 15u) - 8;
        int hi = (int)((bs[j] >> 4) & 15u) - 8;
        h[2 * j]     = __float2half_rn(fmaf((float)lo, s, z));
        h[2 * j + 1] = __float2half_rn(fmaf((float)hi, s, z));
    }
    reinterpret_cast<uint4*>(g_wdeq)[t] = *reinterpret_cast<uint4*>(h);
}

// ---------------- kernel 2: pipelined HMMA GEMM ----------------
__global__ __launch_bounds__(THREADS, 1)
void q4_gemm_kernel(const float* __restrict__ bias,
                    float* __restrict__ out) {
    extern __shared__ char smem[];
    const uint32_t sbase = smem_u32(smem);
    const int tid = threadIdx.x;
    const int lane = tid & 31;
    const int wid = tid >> 5;
    const int warp_m = wid & 3;      // 0..3  -> 64-row slab
    const int warp_n = wid >> 2;     // 0..1  -> 64-col slab
    const int bm = blockIdx.x;       // bm fastest: wave shares B cols, x stays in L2
    const int bn = blockIdx.y;

    const uint4* gA = reinterpret_cast<const uint4*>(g_xh)
                      + (size_t)(bm * BM) * (IN_F / 8);
    const uint4* gB = reinterpret_cast<const uint4*>(g_wdeq)
                      + (size_t)(bn * BN) * (IN_F / 8);

    // smem swizzle: 16B chunk' = c ^ (row & 7)  (conflict-free for ldmatrix)
    const int s7 = lane & 7;
    const uint32_t aRow = (uint32_t)(warp_m * 64 + (lane & 7) + ((lane >> 3) & 1) * 8);
    const int aCo = lane >> 4;                 // k16-chunk half
    const uint32_t bRow = (uint32_t)(warp_n * 64 + (lane & 7) + ((lane >> 4) & 1) * 8);
    const int bCo = (lane >> 3) & 1;

    float acc[4][8][4];
#pragma unroll
    for (int mt = 0; mt < 4; ++mt)
#pragma unroll
        for (int nt = 0; nt < 8; ++nt)
#pragma unroll
            for (int j = 0; j < 4; ++j) acc[mt][nt][j] = 0.f;

#define LOAD_STAGE(BUF, KT)                                                     \
    do {                                                                        \
        const uint32_t abase = sbase + A_OFF + (BUF) * A_STAGE_BYTES;           \
        const uint32_t bbase = sbase + B_OFF + (BUF) * B_STAGE_BYTES;           \
        _Pragma("unroll")                                                       \
        for (int i = 0; i < 8; ++i) {                                           \
            int id = tid + i * 256;                                             \
            int r = id >> 3, c = id & 7;                                        \
            uint32_t sa = abase + r * 128 + ((c ^ (r & 7)) << 4);               \
            CP_ASYNC16(sa, gA + (size_t)r * (IN_F / 8) + (KT) * 8 + c);         \
        }                                                                       \
        _Pragma("unroll")                                                       \
        for (int i = 0; i < 4; ++i) {                                           \
            int id = tid + i * 256;                                             \
            int r = id >> 3, c = id & 7;                                        \
            uint32_t sb = bbase + r * 128 + ((c ^ (r & 7)) << 4);               \
            CP_ASYNC16(sb, gB + (size_t)r * (IN_F / 8) + (KT) * 8 + c);         \
        }                                                                       \
    } while (0)

    LOAD_STAGE(0, 0);
    CP_COMMIT();
    LOAD_STAGE(1, 1);
    CP_COMMIT();

    int buf = 0;
    for (int kt = 0; kt < NK_TILES; ++kt) {
        CP_WAIT1();                 // stage kt resident (own-thread copies)
        __syncthreads();            // whole-block visibility + prev-stage readers done
        const int nk = kt + 2;
        if (nk < NK_TILES) LOAD_STAGE(nk % NSTAGES, nk);
        CP_COMMIT();                // empty groups near the tail are fine

        const uint32_t abase = sbase + A_OFF + buf * A_STAGE_BYTES;
        const uint32_t bbase = sbase + B_OFF + buf * B_STAGE_BYTES;
#pragma unroll
        for (int ks = 0; ks < 4; ++ks) {        // 4 x k16 per BK=64
            uint32_t a[4][4];
#pragma unroll
            for (int mt = 0; mt < 4; ++mt) {
                uint32_t addr = abase + (aRow + mt * 16) * 128
                              + (uint32_t)(((2 * ks + aCo) ^ s7) << 4);
                LDMATRIX_X4(a[mt][0], a[mt][1], a[mt][2], a[mt][3], addr);
            }
            uint32_t b[4][4];   // [nt2][0,1]=frag(2*nt2), [2,3]=frag(2*nt2+1)
#pragma unroll
            for (int nt2 = 0; nt2 < 4; ++nt2) {
                uint32_t addr = bbase + (bRow + nt2 * 16) * 128
                              + (uint32_t)(((2 * ks + bCo) ^ s7) << 4);
                LDMATRIX_X4(b[nt2][0], b[nt2][1], b[nt2][2], b[nt2][3], addr);
            }
#pragma unroll
            for (int mt = 0; mt < 4; ++mt)
#pragma unroll
                for (int nt = 0; nt < 8; ++nt)
                    MMA_16816(acc[mt][nt],
                              a[mt][0], a[mt][1], a[mt][2], a[mt][3],
                              b[nt >> 1][(nt & 1) * 2], b[nt >> 1][(nt & 1) * 2 + 1]);
        }
        buf = (buf == NSTAGES - 1) ? 0 : buf + 1;
    }

    // ------ epilogue: mimic ref rounding: f16(acc) + f16(bias), store f32 ------
    const size_t mBase = (size_t)bm * BM + warp_m * 64 + (lane >> 2);
    const int nBase = bn * BN + warp_n * 64 + 2 * (lane & 3);
#pragma unroll
    for (int mt = 0; mt < 4; ++mt) {
        const size_t m = mBase + mt * 16;
#pragma unroll
        for (int nt = 0; nt < 8; ++nt) {
            const int n = nBase + nt * 8;
            const __half hb0 = __float2half_rn(bias[n]);
            const __half hb1 = __float2half_rn(bias[n + 1]);
            float2 v0, v1;
            v0.x = __half2float(__hadd(__float2half_rn(acc[mt][nt][0]), hb0));
            v0.y = __half2float(__hadd(__float2half_rn(acc[mt][nt][1]), hb1));
            v1.x = __half2float(__hadd(__float2half_rn(acc[mt][nt][2]), hb0));
            v1.y = __half2float(__hadd(__float2half_rn(acc[mt][nt][3]), hb1));
            *reinterpret_cast<float2*>(out + m * OUT_F + n) = v0;
            *reinterpret_cast<float2*>(out + (m + 8) * OUT_F + n) = v1;
        }
    }
}

// ---------------- launch ----------------
extern "C" void kernel_launch(void* const* d_in, const int* in_sizes, int n_in,
                              void* d_out, int out_size) {
    (void)in_sizes; (void)n_in; (void)out_size;
    const float* x      = (const float*)d_in[0];
    const int*   qw     = (const int*)d_in[1];
    const float* scales = (const float*)d_in[2];
    const float* zeros  = (const float*)d_in[3];
    const float* bias   = (const float*)d_in[4];
    float* out = (float*)d_out;

    // 0) x f32 -> f16 scratch (33,554,432 elems, 8/thread)
    convert_x_kernel<<<(M_ROWS * IN_F) / 8 / 256, 256>>>(x);

    // 1) dequantize W -> fp16 scratch
    q4_dequant_kernel<<<N_PACKED / 4 / 256, 256>>>(qw, scales, zeros);

    // 2) HMMA GEMM: grid (32, 86), bm fastest
    cudaFuncSetAttribute(q4_gemm_kernel,
                         cudaFuncAttributeMaxDynamicSharedMemorySize, SMEM_BYTES);
    dim3 grid(M_ROWS / BM, OUT_F / BN);
    q4_gemm_kernel<<<grid, THREADS, SMEM_BYTES>>>(bias, out);
}

// round 6
// speedup vs baseline: 1.0197x; 1.0197x over previous
#include <cuda_runtime.h>
#include <cuda_fp16.h>
#include <cstdint>

// ---------------- problem constants ----------------
#define IN_F    4096
#define OUT_F   11008
#define M_ROWS  8192
#define N_PACKED 22544384          // one packed byte per int32

// ---------------- GEMM tiling ----------------
#define BM 256
#define BN 128
#define BK 64                      // 64 fp16 = 128 B per smem row
#define NSTAGES 4
#define NK_TILES (IN_F / BK)       // 64
#define THREADS 256                // 8 warps: 4 (m) x 2 (n), warp tile 64x64

#define A_STAGE_BYTES (BM * 128)   // 32768
#define B_STAGE_BYTES (BN * 128)   // 16384
#define A_OFF 0
#define B_OFF (NSTAGES * A_STAGE_BYTES)                 // 131072
#define SMEM_BYTES (B_OFF + NSTAGES * B_STAGE_BYTES)    // 196608

// fp16 scratch (device globals = allowed scratch): W 90MB, x 64MB
static __device__ __half g_wdeq[(size_t)IN_F * (size_t)OUT_F];
static __device__ __half g_xh[(size_t)M_ROWS * (size_t)IN_F];

// ---------------- helpers ----------------
__device__ __forceinline__ uint32_t smem_u32(const void* p) {
    uint32_t a;
    asm("{ .reg .u64 t; cvta.to.shared.u64 t, %1; cvt.u32.u64 %0, t; }"
        : "=r"(a) : "l"(p));
    return a;
}

#define CP_ASYNC16(smem_addr, gptr) \
    asm volatile("cp.async.cg.shared.global.L2::128B [%0], [%1], 16;" \
                 :: "r"(smem_addr), "l"(gptr) : "memory")

#define CP_COMMIT() asm volatile("cp.async.commit_group;" ::: "memory")
#define CP_WAIT2()  asm volatile("cp.async.wait_group 2;" ::: "memory")

#define LDMATRIX_X4(r0, r1, r2, r3, addr) \
    asm volatile("ldmatrix.sync.aligned.m8n8.x4.shared.b16 {%0,%1,%2,%3}, [%4];" \
                 : "=r"(r0), "=r"(r1), "=r"(r2), "=r"(r3) : "r"(addr))

#define MMA_16816(c, a0, a1, a2, a3, b0, b1) \
    asm volatile("mma.sync.aligned.m16n8k16.row.col.f32.f16.f16.f32 " \
                 "{%0,%1,%2,%3}, {%4,%5,%6,%7}, {%8,%9}, {%0,%1,%2,%3};" \
                 : "+f"((c)[0]), "+f"((c)[1]), "+f"((c)[2]), "+f"((c)[3]) \
                 : "r"(a0), "r"(a1), "r"(a2), "r"(a3), "r"(b0), "r"(b1))

// ---------------- kernel 0: x f32 -> f16 (exact; x was originally f16) ----
__global__ __launch_bounds__(256)
void convert_x_kernel(const float* __restrict__ x) {
    size_t t = (size_t)blockIdx.x * blockDim.x + threadIdx.x;  // 8 elems/thread
    const float4* src = reinterpret_cast<const float4*>(x) + t * 2;
    float4 f0 = src[0], f1 = src[1];
    __half h[8];
    h[0] = __float2half_rn(f0.x); h[1] = __float2half_rn(f0.y);
    h[2] = __float2half_rn(f0.z); h[3] = __float2half_rn(f0.w);
    h[4] = __float2half_rn(f1.x); h[5] = __float2half_rn(f1.y);
    h[6] = __float2half_rn(f1.z); h[7] = __float2half_rn(f1.w);
    reinterpret_cast<uint4*>(g_xh)[t] = *reinterpret_cast<uint4*>(h);
}

// ---------------- kernel 1: dequant int4 -> fp16 ----------------
__global__ __launch_bounds__(256)
void q4_dequant_kernel(const int* __restrict__ qw,
                       const float* __restrict__ scales,
                       const float* __restrict__ zeros) {
    int t = blockIdx.x * blockDim.x + threadIdx.x;     // < N_PACKED/4
    uint4 q = reinterpret_cast<const uint4*>(qw)[t];
    int g = (t << 3) >> 7;                             // group index
    float s = __ldg(scales + g);
    float z = __ldg(zeros + g);
    unsigned bs[4] = {q.x, q.y, q.z, q.w};
    __half h[8];
#pragma unroll
    for (int j = 0; j < 4; ++j) {
        int lo = (int)(bs[j] & 15u) - 8;
        int hi = (int)((bs[j] >> 4) & 15u) - 8;
        h[2 * j]     = __float2half_rn(fmaf((float)lo, s, z));
        h[2 * j + 1] = __float2half_rn(fmaf((float)hi, s, z));
    }
    reinterpret_cast<uint4*>(g_wdeq)[t] = *reinterpret_cast<uint4*>(h);
}

// ---------------- kernel 2: pipelined HMMA GEMM ----------------
__global__ __launch_bounds__(THREADS, 1)
void q4_gemm_kernel(const float* __restrict__ bias,
                    float* __restrict__ out) {
    extern __shared__ char smem[];
    const uint32_t sbase = smem_u32(smem);
    const int tid = threadIdx.x;
    const int lane = tid & 31;
    const int wid = tid >> 5;
    const int warp_m = wid & 3;      // 0..3  -> 64-row slab
    const int warp_n = wid >> 2;     // 0..1  -> 64-col slab
    const int bm = blockIdx.x;       // bm fastest: wave shares B cols; x stays in L2
    const int bn = blockIdx.y;

    // ---- hoisted loader addressing (per-thread constants) ----
    // chunk id = tid + i*256; row = id>>3, col-chunk c = id&7 (16B chunks)
    // swizzle: chunk' = c ^ (row & 7)
    const int r0q = tid >> 3;        // base row for i=0 (rows advance by 32 per i)
    const int cq = tid & 7;
    const uint32_t sw_off = (uint32_t)(r0q * 128 + ((cq ^ (r0q & 7)) << 4));
    // note: row parity (r & 7) depends only on r0q&7 since rows step by 32.
    const uint4* gA0 = reinterpret_cast<const uint4*>(g_xh)
                       + (size_t)(bm * BM + r0q) * (IN_F / 8) + cq;
    const uint4* gB0 = reinterpret_cast<const uint4*>(g_wdeq)
                       + (size_t)(bn * BN + r0q) * (IN_F / 8) + cq;

    // ldmatrix lane addressing
    const int s7 = lane & 7;
    const uint32_t aRow = (uint32_t)(warp_m * 64 + (lane & 7) + ((lane >> 3) & 1) * 8);
    const int aCo = lane >> 4;                 // k16-chunk half
    const uint32_t bRow = (uint32_t)(warp_n * 64 + (lane & 7) + ((lane >> 4) & 1) * 8);
    const int bCo = (lane >> 3) & 1;

    float acc[4][8][4];
#pragma unroll
    for (int mt = 0; mt < 4; ++mt)
#pragma unroll
        for (int nt = 0; nt < 8; ++nt)
#pragma unroll
            for (int j = 0; j < 4; ++j) acc[mt][nt][j] = 0.f;

    // per-stage smem bases for this thread's stores
#define LOAD_STAGE(BUF, KT)                                                      \
    do {                                                                         \
        const uint32_t sa = sbase + A_OFF + (BUF) * A_STAGE_BYTES + sw_off;      \
        const uint32_t sb = sbase + B_OFF + (BUF) * B_STAGE_BYTES + sw_off;      \
        const uint4* pa = gA0 + (KT) * 8;                                        \
        const uint4* pb = gB0 + (KT) * 8;                                        \
        _Pragma("unroll")                                                        \
        for (int i = 0; i < 8; ++i)                                              \
            CP_ASYNC16(sa + i * (32 * 128), pa + (size_t)(32 * i) * (IN_F / 8)); \
        _Pragma("unroll")                                                        \
        for (int i = 0; i < 4; ++i)                                              \
            CP_ASYNC16(sb + i * (32 * 128), pb + (size_t)(32 * i) * (IN_F / 8)); \
    } while (0)

    LOAD_STAGE(0, 0); CP_COMMIT();
    LOAD_STAGE(1, 1); CP_COMMIT();
    LOAD_STAGE(2, 2); CP_COMMIT();

    int buf = 0;
    for (int kt = 0; kt < NK_TILES; ++kt) {
        CP_WAIT2();                 // stage kt resident (<=2 groups pending)
        __syncthreads();            // visibility + prev readers done with this buf
        const int nk = kt + 3;
        if (nk < NK_TILES) { LOAD_STAGE(nk & 3, nk); }
        CP_COMMIT();                // keep group count in lockstep (empty ok)

        const uint32_t abase = sbase + A_OFF + buf * A_STAGE_BYTES;
        const uint32_t bbase = sbase + B_OFF + buf * B_STAGE_BYTES;
#pragma unroll
        for (int ks = 0; ks < 4; ++ks) {        // 4 x k16 per BK=64
            uint32_t a[4][4];
#pragma unroll
            for (int mt = 0; mt < 4; ++mt) {
                uint32_t addr = abase + (aRow + mt * 16) * 128
                              + (uint32_t)(((2 * ks + aCo) ^ s7) << 4);
                LDMATRIX_X4(a[mt][0], a[mt][1], a[mt][2], a[mt][3], addr);
            }
            uint32_t b[4][4];   // [nt2][0,1]=frag(2*nt2), [2,3]=frag(2*nt2+1)
#pragma unroll
            for (int nt2 = 0; nt2 < 4; ++nt2) {
                uint32_t addr = bbase + (bRow + nt2 * 16) * 128
                              + (uint32_t)(((2 * ks + bCo) ^ s7) << 4);
                LDMATRIX_X4(b[nt2][0], b[nt2][1], b[nt2][2], b[nt2][3], addr);
            }
#pragma unroll
            for (int mt = 0; mt < 4; ++mt)
#pragma unroll
                for (int nt = 0; nt < 8; ++nt)
                    MMA_16816(acc[mt][nt],
                              a[mt][0], a[mt][1], a[mt][2], a[mt][3],
                              b[nt >> 1][(nt & 1) * 2], b[nt >> 1][(nt & 1) * 2 + 1]);
        }
        buf = (buf + 1) & 3;
    }

    // ------ epilogue: mimic ref rounding: f16(acc) + f16(bias), store f32 ------
    const size_t mBase = (size_t)bm * BM + warp_m * 64 + (lane >> 2);
    const int nBase = bn * BN + warp_n * 64 + 2 * (lane & 3);
#pragma unroll
    for (int mt = 0; mt < 4; ++mt) {
        const size_t m = mBase + mt * 16;
#pragma unroll
        for (int nt = 0; nt < 8; ++nt) {
            const int n = nBase + nt * 8;
            const __half hb0 = __float2half_rn(bias[n]);
            const __half hb1 = __float2half_rn(bias[n + 1]);
            float2 v0, v1;
            v0.x = __half2float(__hadd(__float2half_rn(acc[mt][nt][0]), hb0));
            v0.y = __half2float(__hadd(__float2half_rn(acc[mt][nt][1]), hb1));
            v1.x = __half2float(__hadd(__float2half_rn(acc[mt][nt][2]), hb0));
            v1.y = __half2float(__hadd(__float2half_rn(acc[mt][nt][3]), hb1));
            *reinterpret_cast<float2*>(out + m * OUT_F + n) = v0;
            *reinterpret_cast<float2*>(out + (m + 8) * OUT_F + n) = v1;
        }
    }
}

// ---------------- launch ----------------
extern "C" void kernel_launch(void* const* d_in, const int* in_sizes, int n_in,
                              void* d_out, int out_size) {
    (void)in_sizes; (void)n_in; (void)out_size;
    const float* x      = (const float*)d_in[0];
    const int*   qw     = (const int*)d_in[1];
    const float* scales = (const float*)d_in[2];
    const float* zeros  = (const float*)d_in[3];
    const float* bias   = (const float*)d_in[4];
    float* out = (float*)d_out;

    // 0) x f32 -> f16 scratch
    convert_x_kernel<<<(M_ROWS * IN_F) / 8 / 256, 256>>>(x);

    // 1) dequantize W -> fp16 scratch
    q4_dequant_kernel<<<N_PACKED / 4 / 256, 256>>>(qw, scales, zeros);

    // 2) HMMA GEMM: grid (32, 86), bm fastest
    cudaFuncSetAttribute(q4_gemm_kernel,
                         cudaFuncAttributeMaxDynamicSharedMemorySize, SMEM_BYTES);
    dim3 grid(M_ROWS / BM, OUT_F / BN);
    q4_gemm_kernel<<<grid, THREADS, SMEM_BYTES>>>(bias, out);
}